// round 12
// baseline (speedup 1.0000x reference)
#include <cuda_runtime.h>
#include <cstdint>

#define BB 16
#define TT 512
#define NB 16
#define CH 8

typedef unsigned long long ull;

// ---------------- packed f32x2 helpers ----------------
__device__ __forceinline__ ull pk2(float a, float b){
    ull r; asm("mov.b64 %0, {%1,%2};" : "=l"(r) : "f"(a), "f"(b)); return r; }
__device__ __forceinline__ void upk2(ull v, float& a, float& b){
    asm("mov.b64 {%0,%1}, %2;" : "=f"(a), "=f"(b) : "l"(v)); }
__device__ __forceinline__ void fma2(ull& d, ull a, ull b){
    asm("fma.rn.f32x2 %0, %1, %2, %0;" : "+l"(d) : "l"(a), "l"(b)); }
__device__ __forceinline__ ull mul2(ull a, ull b){
    ull r; asm("mul.rn.f32x2 %0, %1, %2;" : "=l"(r) : "l"(a), "l"(b)); return r; }
__device__ __forceinline__ void add2(ull& d, ull a){
    asm("add.rn.f32x2 %0, %0, %1;" : "+l"(d) : "l"(a)); }
__device__ __forceinline__ float ex2f(float x){
    float r; asm("ex2.approx.f32 %0, %1;" : "=f"(r) : "f"(x)); return r; }

#define QS  (0.70710678118654752f * 1.4426950408889634f)
#define CS  (0.35355339059327376f * 1.4426950408889634f)

// ---------------- scratch ----------------
__device__ __align__(16) float g_q  [BB*NB*2*TT*2];
__device__ __align__(16) float g_kv [BB*NB*2*TT*4];
__device__ __align__(16) float g_o  [BB*TT*64];
__device__ __align__(16) float g_ab [BB*TT*64];
__device__ __align__(16) float g_cq [BB*CH*TT*8];
__device__ __align__(16) float g_ck [BB*CH*TT*8];
__device__ __align__(16) float g_cv [BB*CH*TT*8];
__device__ __align__(16) float g_co [BB*TT*64];
__device__ __align__(16) float g_linv[BB*CH*TT];
__device__ __align__(16) float g_entp[BB*TT*16];
__device__ __align__(16) float g_po [BB*CH*4*TT*8];   // partial o: [c][split4][t][8]
__device__ __align__(16) float g_pl [BB*CH*4*TT];     // partial l

__device__ __align__(16) float g_cwqkvT[64*192];
__device__ __align__(16) float g_cwoutT[64*64];
__device__ __align__(16) float g_fw1T[64*256];
__device__ __align__(16) float g_fw2T[256*64];

__device__ __forceinline__ float gelu_f(float x){
    return 0.5f * x * (1.0f + erff(x * 0.70710678118654752f));
}

#define K1_BLOCKS (BB*TT/4)   // 2048
#define TR_BLOCKS 48

// ---------------- K1: block extraction + tiny QKV (4 tok/block) + transpose tail ----------------
__global__ void __launch_bounds__(256) k1_blockqkv(const float* __restrict__ M,
                            const float* __restrict__ w,
                            const float* __restrict__ bias,
                            const float* __restrict__ cwqkv,
                            const float* __restrict__ cwout,
                            const float* __restrict__ fw1,
                            const float* __restrict__ fw2){
    int tid = threadIdx.x;
    if (blockIdx.x >= K1_BLOCKS){
        int stride = TR_BLOCKS * 256;
        int tid0 = (blockIdx.x - K1_BLOCKS) * 256 + tid;
        for (int idx = tid0; idx < 64*192; idx += stride){
            int j = idx / 192, o = idx - j*192;
            g_cwqkvT[idx] = cwqkv[o*64 + j];
        }
        for (int idx = tid0; idx < 64*64; idx += stride){
            int j = idx >> 6, o = idx & 63;
            g_cwoutT[idx] = cwout[o*64 + j];
        }
        for (int idx = tid0; idx < 64*256; idx += stride){
            int j = idx >> 8, o = idx & 255;
            g_fw1T[idx] = fw1[o*64 + j];
        }
        for (int idx = tid0; idx < 256*64; idx += stride){
            int j = idx >> 6, o = idx & 63;
            g_fw2T[idx] = fw2[o*256 + j];
        }
        return;
    }
    int bt0 = blockIdx.x * 4;
    int b = bt0 >> 9;
    __shared__ float mrow[256];
    mrow[tid] = M[bt0*64 + tid];
    __syncthreads();
    #pragma unroll
    for (int it = 0; it < 3; it++){
        int idx = tid + it*256;
        int tok = idx / 192, r = idx - tok*192;
        int t = (bt0 + tok) & 511;
        int n = r / 12, e = r - n*12;
        int br = n >> 2, bc = n & 3;
        int base = tok*64 + 16*br + 2*bc;
        float x0 = mrow[base], x1 = mrow[base+1], x2 = mrow[base+8], x3 = mrow[base+9];
        const float* wp = w + r*4;
        float val = bias[r] + wp[0]*x0 + wp[1]*x1 + wp[2]*x2 + wp[3]*x3;
        if (e < 4){
            int h = e >> 1, d = e & 1;
            g_q[(((b*NB+n)*2+h)*TT + t)*2 + d] = val * QS;
        } else if (e < 8){
            int ee = e - 4; int h = ee >> 1, d = ee & 1;
            g_kv[((b*NB+n)*2+h)*TT*4 + (t>>1)*8 + d*2 + (t&1)] = val;
        } else {
            int ee = e - 8; int h = ee >> 1, d = ee & 1;
            g_kv[((b*NB+n)*2+h)*TT*4 + (t>>1)*8 + 4 + d*2 + (t&1)] = val;
        }
    }
}

// ---------------- K2: 512 tiny attentions (d=2), paired ----------------
__global__ void __launch_bounds__(TT) k2_blockattn(){
    int c = blockIdx.x;                // 512
    __shared__ __align__(16) float sKV[TT*4];
    int t = threadIdx.x;
    ((float4*)sKV)[t] = ((const float4*)g_kv)[c*TT + t];
    __syncthreads();
    float2 q = ((const float2*)g_q)[c*TT + t];
    ull qxx = pk2(q.x, q.x), qyy = pk2(q.y, q.y);
    ull l2 = 0ull, oz2 = 0ull, ow2 = 0ull;
    const ulonglong2* s2 = (const ulonglong2*)sKV;
    #pragma unroll 8
    for (int p = 0; p < 256; p++){
        ulonglong2 kk = s2[p*2];
        ulonglong2 vv = s2[p*2+1];
        ull sc2 = mul2(qxx, kk.x);
        fma2(sc2, qyy, kk.y);
        float s0, s1; upk2(sc2, s0, s1);
        ull pp = pk2(ex2f(s0), ex2f(s1));
        add2(l2, pp);
        fma2(oz2, pp, vv.x);
        fma2(ow2, pp, vv.y);
    }
    float la, lb, za, zb, wa, wb;
    upk2(l2, la, lb); upk2(oz2, za, zb); upk2(ow2, wa, wb);
    float inv = __fdividef(1.f, la + lb);
    int b = c >> 5, n = (c >> 1) & 15, h = c & 1;
    ((float2*)g_o)[(b*TT + t)*32 + n*2 + h] = make_float2((za+zb)*inv, (wa+wb)*inv);
}

// ---------------- K4: block out-proj + cross QKV, 4 tok/block ----------------
__global__ void __launch_bounds__(192) k4_crossqkv(const float* __restrict__ bw,
                                                   const float* __restrict__ bb,
                                                   const float* __restrict__ bias){
    int bt0 = blockIdx.x * 4;
    int b = bt0 >> 9;
    int tid = threadIdx.x;
    __shared__ __align__(16) float s_xT[64*4];

    for (int idx = tid; idx < 256; idx += 192){
        int tok = idx >> 6, o = idx & 63;
        int n = o >> 2;
        float4 ov = ((const float4*)g_o)[(bt0+tok)*16 + n];
        float4 wv = ((const float4*)bw)[o];
        float acc = bb[o];
        acc = fmaf(wv.x, ov.x, acc); acc = fmaf(wv.y, ov.y, acc);
        acc = fmaf(wv.z, ov.z, acc); acc = fmaf(wv.w, ov.w, acc);
        s_xT[o*4 + tok] = acc;
        g_ab[(bt0+tok)*64 + o] = acc;
    }
    __syncthreads();

    float bs = bias[tid];
    ull acc0 = pk2(bs, bs), acc1 = pk2(bs, bs);
    #pragma unroll 8
    for (int j = 0; j < 64; j++){
        float w = g_cwqkvT[j*192 + tid];
        ull ww = pk2(w, w);
        ulonglong2 xx = *(const ulonglong2*)&s_xT[j*4];
        fma2(acc0, ww, xx.x); fma2(acc1, ww, xx.y);
    }
    float av[4];
    upk2(acc0, av[0], av[1]); upk2(acc1, av[2], av[3]);
    #pragma unroll
    for (int tok = 0; tok < 4; tok++){
        int t = (bt0 + tok) & 511;
        float v = av[tok];
        if (tid < 64){
            int h = tid >> 3, d = tid & 7;
            g_cq[((b*CH+h)*TT + t)*8 + d] = v * CS;
        } else if (tid < 128){
            int i = tid - 64; int h = i >> 3, d = i & 7;
            g_ck[(b*CH+h)*TT*8 + (t>>1)*16 + d*2 + (t&1)] = v;
        } else {
            int i = tid - 128; int h = i >> 3, d = i & 7;
            g_cv[(b*CH+h)*TT*8 + (t>>1)*16 + d*2 + (t&1)] = v;
        }
    }
}

// ---------------- K5: cross attention (d=8), 4-way s-split, split score chain ----------------
__global__ void __launch_bounds__(128) k5_crossattn(){
    int blk = blockIdx.x;              // 2048 = c(128) x sh(4) x tq(4)
    int c  = blk >> 4;
    int sh = (blk >> 2) & 3;
    int t  = (blk & 3)*128 + threadIdx.x;
    __shared__ __align__(16) float sK[128*8];
    __shared__ __align__(16) float sV[128*8];
    {
        const float4* kp = (const float4*)(g_ck + c*TT*8 + sh*1024);
        const float4* vp = (const float4*)(g_cv + c*TT*8 + sh*1024);
        for (int i = threadIdx.x; i < 256; i += 128){
            ((float4*)sK)[i] = kp[i];
            ((float4*)sV)[i] = vp[i];
        }
    }
    __syncthreads();
    ull qjj[8];
    {
        float4 qa = ((const float4*)g_cq)[(c*TT + t)*2];
        float4 qb = ((const float4*)g_cq)[(c*TT + t)*2 + 1];
        qjj[0]=pk2(qa.x,qa.x); qjj[1]=pk2(qa.y,qa.y); qjj[2]=pk2(qa.z,qa.z); qjj[3]=pk2(qa.w,qa.w);
        qjj[4]=pk2(qb.x,qb.x); qjj[5]=pk2(qb.y,qb.y); qjj[6]=pk2(qb.z,qb.z); qjj[7]=pk2(qb.w,qb.w);
    }
    ull l2 = 0ull;
    ull o2[8];
    #pragma unroll
    for (int j = 0; j < 8; j++) o2[j] = 0ull;
    const ulonglong2* kp2 = (const ulonglong2*)sK;
    const ulonglong2* vp2 = (const ulonglong2*)sV;
    #pragma unroll 4
    for (int p = 0; p < 64; p++){
        ulonglong2 k0 = kp2[p*4], k1 = kp2[p*4+1], k2v = kp2[p*4+2], k3 = kp2[p*4+3];
        // split score chain: two independent halves
        ull sca = mul2(qjj[0], k0.x);
        ull scb = mul2(qjj[4], k2v.x);
        fma2(sca, qjj[1], k0.y); fma2(scb, qjj[5], k2v.y);
        fma2(sca, qjj[2], k1.x); fma2(scb, qjj[6], k3.x);
        fma2(sca, qjj[3], k1.y); fma2(scb, qjj[7], k3.y);
        add2(sca, scb);
        float s0, s1; upk2(sca, s0, s1);
        ull pp = pk2(ex2f(s0), ex2f(s1));
        add2(l2, pp);
        ulonglong2 v0 = vp2[p*4], v1 = vp2[p*4+1], v2v = vp2[p*4+2], v3 = vp2[p*4+3];
        fma2(o2[0], pp, v0.x); fma2(o2[1], pp, v0.y);
        fma2(o2[2], pp, v1.x); fma2(o2[3], pp, v1.y);
        fma2(o2[4], pp, v2v.x); fma2(o2[5], pp, v2v.y);
        fma2(o2[6], pp, v3.x); fma2(o2[7], pp, v3.y);
    }
    float la, lb; upk2(l2, la, lb);
    int pidx = (c*4 + sh)*TT + t;
    g_pl[pidx] = la + lb;
    float ov[8];
    #pragma unroll
    for (int j = 0; j < 8; j++){
        float oa, ob; upk2(o2[j], oa, ob);
        ov[j] = oa + ob;
    }
    float4* pop = (float4*)(g_po + pidx*8);
    pop[0] = make_float4(ov[0], ov[1], ov[2], ov[3]);
    pop[1] = make_float4(ov[4], ov[5], ov[6], ov[7]);
}

// ---------------- K5b: combine 4-way partials ----------------
__global__ void __launch_bounds__(512) k5b_combine(){
    int c = blockIdx.x;                // 128
    int t = threadIdx.x;
    int p0 = c*4*TT + t;
    float4 s0a = ((const float4*)g_po)[(p0)*2],        s0b = ((const float4*)g_po)[(p0)*2 + 1];
    float4 s1a = ((const float4*)g_po)[(p0+TT)*2],     s1b = ((const float4*)g_po)[(p0+TT)*2 + 1];
    float4 s2a = ((const float4*)g_po)[(p0+2*TT)*2],   s2b = ((const float4*)g_po)[(p0+2*TT)*2 + 1];
    float4 s3a = ((const float4*)g_po)[(p0+3*TT)*2],   s3b = ((const float4*)g_po)[(p0+3*TT)*2 + 1];
    float l = (g_pl[p0] + g_pl[p0+TT]) + (g_pl[p0+2*TT] + g_pl[p0+3*TT]);
    float inv = __fdividef(1.f, l);
    g_linv[c*TT + t] = inv;
    int b = c >> 3, h = c & 7;
    float4* cop = (float4*)(g_co + (b*TT + t)*64 + h*8);
    cop[0] = make_float4(((s0a.x+s1a.x)+(s2a.x+s3a.x))*inv, ((s0a.y+s1a.y)+(s2a.y+s3a.y))*inv,
                         ((s0a.z+s1a.z)+(s2a.z+s3a.z))*inv, ((s0a.w+s1a.w)+(s2a.w+s3a.w))*inv);
    cop[1] = make_float4(((s0b.x+s1b.x)+(s2b.x+s3b.x))*inv, ((s0b.y+s1b.y)+(s2b.y+s3b.y))*inv,
                         ((s0b.z+s1b.z)+(s2b.z+s3b.z))*inv, ((s0b.w+s1b.w)+(s2b.w+s3b.w))*inv);
}

// ---------------- K6: entropy by recompute ----------------
__global__ void __launch_bounds__(128) k6_entropy(){
    int blk = blockIdx.x;              // 1024 = b(16) * tile(4) * chunk(16)
    int b = blk >> 6;
    int tile = (blk >> 4) & 3;
    int chunk = blk & 15;
    int t = tile*128 + threadIdx.x;
    __shared__ __align__(16) float sK[8*256];
    for (int i = threadIdx.x; i < 512; i += 128){
        int h = i >> 6, f = i & 63;
        ((float4*)sK)[i] = ((const float4*)g_ck)[(b*CH+h)*1024 + chunk*64 + f];
    }
    __syncthreads();
    ull pm2[16];
    #pragma unroll
    for (int p = 0; p < 16; p++) pm2[p] = 0ull;
    #pragma unroll
    for (int h = 0; h < 8; h++){
        float4 qa = ((const float4*)g_cq)[((b*CH+h)*TT + t)*2];
        float4 qb = ((const float4*)g_cq)[((b*CH+h)*TT + t)*2 + 1];
        ull q0=pk2(qa.x,qa.x), q1=pk2(qa.y,qa.y), q2=pk2(qa.z,qa.z), q3=pk2(qa.w,qa.w);
        ull q4=pk2(qb.x,qb.x), q5=pk2(qb.y,qb.y), q6=pk2(qb.z,qb.z), q7=pk2(qb.w,qb.w);
        float il = g_linv[(b*CH+h)*TT + t] * 0.125f;
        ull ivv = pk2(il, il);
        const ulonglong2* kh = (const ulonglong2*)(sK + h*256);
        #pragma unroll
        for (int p = 0; p < 16; p++){
            ulonglong2 k0 = kh[p*4], k1 = kh[p*4+1], k2v = kh[p*4+2], k3 = kh[p*4+3];
            ull sc2 = mul2(q0, k0.x);
            fma2(sc2, q1, k0.y); fma2(sc2, q2, k1.x); fma2(sc2, q3, k1.y);
            fma2(sc2, q4, k2v.x); fma2(sc2, q5, k2v.y);
            fma2(sc2, q6, k3.x); fma2(sc2, q7, k3.y);
            float s0, s1; upk2(sc2, s0, s1);
            ull pp = pk2(ex2f(s0), ex2f(s1));
            fma2(pm2[p], pp, ivv);
        }
    }
    float acc = 0.f;
    #pragma unroll
    for (int p = 0; p < 16; p++){
        float m0, m1; upk2(pm2[p], m0, m1);
        acc = fmaf(m0, __logf(m0 + 1e-9f), acc);
        acc = fmaf(m1, __logf(m1 + 1e-9f), acc);
    }
    g_entp[(b*TT + t)*16 + chunk] = acc;
}

// ---------------- K7: fused epilogue, 8 tok/block, packed GEMMs ----------------
__global__ void __launch_bounds__(256) k7_fused(
    const float* __restrict__ M, const int* __restrict__ token_ids,
    const float* __restrict__ cbout,
    const float* __restrict__ g1, const float* __restrict__ be1,
    const float* __restrict__ fb1,
    const float* __restrict__ fb2,
    const float* __restrict__ g2, const float* __restrict__ be2,
    const float* __restrict__ sbase, const float* __restrict__ taff,
    const float* __restrict__ sw1, const float* __restrict__ sb1,
    const float* __restrict__ sw2, const float* __restrict__ sb2,
    float* __restrict__ out)
{
    int bt0 = blockIdx.x * 8;
    int tid = threadIdx.x;
    int lane = tid & 31, warp = tid >> 5;

    __shared__ __align__(16) float s_coT[64*8];
    __shared__ __align__(16) float s_abT[64*8];
    __shared__ __align__(16) float s_yT [64*8];
    __shared__ __align__(16) float s_xT [64*8];
    __shared__ __align__(16) float s_x2T[64*8];
    __shared__ __align__(16) float s_h1T[256*8];
    __shared__ __align__(16) float s_fp [4*64*8];
    __shared__ float s_mu[8], s_rs[8];
    __shared__ float s_ent[8];
    __shared__ float s_hs[8*32];
    __shared__ float s_sens[8*16];

    for (int idx = tid; idx < 512; idx += 256){
        int tok = idx >> 6, o = idx & 63;
        s_coT[o*8 + tok] = g_co[(bt0+tok)*64 + o];
        s_abT[o*8 + tok] = g_ab[(bt0+tok)*64 + o];
    }
    __syncthreads();

    int o64 = tid & 63, qr = tid >> 6;

    // cross out-proj (j split 4-ways, packed)
    {
        ull acc[4] = {0ull, 0ull, 0ull, 0ull};
        int j0 = qr*16;
        #pragma unroll
        for (int j = j0; j < j0+16; j++){
            float w = g_cwoutT[j*64 + o64];
            ull ww = pk2(w, w);
            const ull* cp = (const ull*)&s_coT[j*8];
            fma2(acc[0], ww, cp[0]); fma2(acc[1], ww, cp[1]);
            fma2(acc[2], ww, cp[2]); fma2(acc[3], ww, cp[3]);
        }
        ull* fp = (ull*)&s_fp[qr*512 + o64*8];
        fp[0]=acc[0]; fp[1]=acc[1]; fp[2]=acc[2]; fp[3]=acc[3];
    }
    __syncthreads();
    for (int idx = tid; idx < 512; idx += 256){
        int o = idx >> 3, tok = idx & 7;
        s_yT[o*8 + tok] = cbout[o] + s_abT[o*8+tok]
                + s_fp[o*8+tok] + s_fp[512 + o*8+tok]
                + s_fp[1024 + o*8+tok] + s_fp[1536 + o*8+tok];
    }
    __syncthreads();

    // LN1 stats
    {
        float v0 = s_yT[lane*8 + warp];
        float v1 = s_yT[(lane+32)*8 + warp];
        float sv = v0 + v1, sq = v0*v0 + v1*v1;
        #pragma unroll
        for (int off = 16; off > 0; off >>= 1){
            sv += __shfl_down_sync(0xffffffffu, sv, off);
            sq += __shfl_down_sync(0xffffffffu, sq, off);
        }
        if (lane == 0){
            float mean = sv * (1.f/64.f);
            float var  = sq * (1.f/64.f) - mean*mean;
            s_mu[warp] = mean;
            s_rs[warp] = rsqrtf(var + 1e-5f);
        }
    }
    __syncthreads();
    for (int idx = tid; idx < 512; idx += 256){
        int o = idx >> 3, tok = idx & 7;
        s_xT[o*8+tok] = (s_yT[o*8+tok] - s_mu[tok]) * s_rs[tok] * g1[o] + be1[o];
    }
    __syncthreads();

    // FFN1 (packed)
    {
        float bs = fb1[tid];
        ull acc[4];
        #pragma unroll
        for (int k = 0; k < 4; k++) acc[k] = pk2(bs, bs);
        #pragma unroll 8
        for (int j = 0; j < 64; j++){
            float w = g_fw1T[j*256 + tid];
            ull ww = pk2(w, w);
            const ulonglong2* xp = (const ulonglong2*)&s_xT[j*8];
            ulonglong2 x0 = xp[0], x1 = xp[1];
            fma2(acc[0], ww, x0.x); fma2(acc[1], ww, x0.y);
            fma2(acc[2], ww, x1.x); fma2(acc[3], ww, x1.y);
        }
        ull* hp = (ull*)&s_h1T[tid*8];
        #pragma unroll
        for (int k = 0; k < 4; k++){
            float a, bvl; upk2(acc[k], a, bvl);
            hp[k] = pk2(gelu_f(a), gelu_f(bvl));
        }
    }
    __syncthreads();

    // FFN2 (j split 4-ways, packed)
    {
        ull acc[4] = {0ull, 0ull, 0ull, 0ull};
        int j0 = qr*64;
        #pragma unroll 8
        for (int j = j0; j < j0+64; j++){
            float w = g_fw2T[j*64 + o64];
            ull ww = pk2(w, w);
            const ull* hp = (const ull*)&s_h1T[j*8];
            fma2(acc[0], ww, hp[0]); fma2(acc[1], ww, hp[1]);
            fma2(acc[2], ww, hp[2]); fma2(acc[3], ww, hp[3]);
        }
        ull* fp = (ull*)&s_fp[qr*512 + o64*8];
        fp[0]=acc[0]; fp[1]=acc[1]; fp[2]=acc[2]; fp[3]=acc[3];
    }
    __syncthreads();
    for (int idx = tid; idx < 512; idx += 256){
        int o = idx >> 3, tok = idx & 7;
        s_yT[o*8 + tok] = s_xT[o*8+tok] + fb2[o]
                + s_fp[o*8+tok] + s_fp[512 + o*8+tok]
                + s_fp[1024 + o*8+tok] + s_fp[1536 + o*8+tok];
    }
    __syncthreads();

    // LN2 stats
    {
        float v0 = s_yT[lane*8 + warp];
        float v1 = s_yT[(lane+32)*8 + warp];
        float sv = v0 + v1, sq = v0*v0 + v1*v1;
        #pragma unroll
        for (int off = 16; off > 0; off >>= 1){
            sv += __shfl_down_sync(0xffffffffu, sv, off);
            sq += __shfl_down_sync(0xffffffffu, sq, off);
        }
        if (lane == 0){
            float mean = sv * (1.f/64.f);
            float var  = sq * (1.f/64.f) - mean*mean;
            s_mu[warp] = mean;
            s_rs[warp] = rsqrtf(var + 1e-5f);
        }
    }
    __syncthreads();
    for (int idx = tid; idx < 512; idx += 256){
        int o = idx >> 3, tok = idx & 7;
        s_x2T[o*8+tok] = (s_yT[o*8+tok] - s_mu[tok]) * s_rs[tok] * g2[o] + be2[o];
    }
    if (tid < 8){
        float e = 0.f;
        #pragma unroll
        for (int c = 0; c < 16; c++) e += g_entp[(bt0+tid)*16 + c];
        s_ent[tid] = -e;
    }
    __syncthreads();

    // sensitivity MLP
    {
        int tok = tid >> 5, hh = tid & 31;
        int tk = token_ids[bt0 + tok];
        float acc = sb1[hh];
        const float* wp = sw1 + hh*17;
        const float* ap = taff + (size_t)tk*16;
        #pragma unroll
        for (int a = 0; a < 16; a++) acc = fmaf(wp[a], ap[a], acc);
        acc = fmaf(wp[16], s_ent[tok], acc);
        s_hs[tok*32 + hh] = gelu_f(acc);
    }
    __syncthreads();
    if (tid < 128){
        int tok = tid >> 4, oo = tid & 15;
        float acc = sb2[oo];
        const float* wp = sw2 + oo*32;
        #pragma unroll
        for (int j = 0; j < 32; j++) acc = fmaf(wp[j], s_hs[tok*32 + j], acc);
        s_sens[tok*16 + oo] = sbase[oo] / (1.f + __expf(-acc));
    }
    __syncthreads();

    for (int idx = tid; idx < 512; idx += 256){
        int tok = idx >> 6, o = idx & 63;
        float m = M[(bt0+tok)*64 + o];
        out[(bt0+tok)*64 + o] = fmaf(s_x2T[o*8+tok] - m, s_sens[tok*16 + (o>>2)], m);
    }
}

// ---------------- launch ----------------
extern "C" void kernel_launch(void* const* d_in, const int* in_sizes, int n_in,
                              void* d_out, int out_size){
    const float* M     = (const float*)d_in[0];
    const int*   tok   = (const int*)  d_in[1];
    const float* bwqkv = (const float*)d_in[2];
    const float* bbqkv = (const float*)d_in[3];
    const float* bwout = (const float*)d_in[4];
    const float* bbout = (const float*)d_in[5];
    const float* cwqkv = (const float*)d_in[6];
    const float* cbqkv = (const float*)d_in[7];
    const float* cwout = (const float*)d_in[8];
    const float* cbout = (const float*)d_in[9];
    const float* g1    = (const float*)d_in[10];
    const float* b1    = (const float*)d_in[11];
    const float* fw1   = (const float*)d_in[12];
    const float* fb1   = (const float*)d_in[13];
    const float* fw2   = (const float*)d_in[14];
    const float* fb2   = (const float*)d_in[15];
    const float* g2    = (const float*)d_in[16];
    const float* b2    = (const float*)d_in[17];
    const float* sbase = (const float*)d_in[18];
    const float* taff  = (const float*)d_in[19];
    const float* sw1   = (const float*)d_in[20];
    const float* sb1   = (const float*)d_in[21];
    const float* sw2   = (const float*)d_in[22];
    const float* sb2   = (const float*)d_in[23];

    k1_blockqkv<<<K1_BLOCKS + TR_BLOCKS, 256>>>(M, bwqkv, bbqkv, cwqkv, cwout, fw1, fw2);
    k2_blockattn<<<512, TT>>>();
    k4_crossqkv<<<BB*TT/4, 192>>>(bwout, bbout, cbqkv);
    k5_crossattn<<<2048, 128>>>();
    k5b_combine<<<128, 512>>>();
    k6_entropy<<<1024, 128>>>();
    k7_fused<<<BB*TT/8, 256>>>(M, tok, cbout, g1, b1, fb1, fb2, g2, b2,
                               sbase, taff, sw1, sb1, sw2, sb2, (float*)d_out);
}

// round 13
// speedup vs baseline: 1.0119x; 1.0119x over previous
#include <cuda_runtime.h>
#include <cstdint>

#define BB 16
#define TT 512
#define NB 16
#define CH 8

typedef unsigned long long ull;

// ---------------- packed f32x2 helpers ----------------
__device__ __forceinline__ ull pk2(float a, float b){
    ull r; asm("mov.b64 %0, {%1,%2};" : "=l"(r) : "f"(a), "f"(b)); return r; }
__device__ __forceinline__ void upk2(ull v, float& a, float& b){
    asm("mov.b64 {%0,%1}, %2;" : "=f"(a), "=f"(b) : "l"(v)); }
__device__ __forceinline__ void fma2(ull& d, ull a, ull b){
    asm("fma.rn.f32x2 %0, %1, %2, %0;" : "+l"(d) : "l"(a), "l"(b)); }
__device__ __forceinline__ ull mul2(ull a, ull b){
    ull r; asm("mul.rn.f32x2 %0, %1, %2;" : "=l"(r) : "l"(a), "l"(b)); return r; }
__device__ __forceinline__ void add2(ull& d, ull a){
    asm("add.rn.f32x2 %0, %0, %1;" : "+l"(d) : "l"(a)); }
__device__ __forceinline__ float ex2f(float x){
    float r; asm("ex2.approx.f32 %0, %1;" : "=f"(r) : "f"(x)); return r; }

#define QS  (0.70710678118654752f * 1.4426950408889634f)
#define CS  (0.35355339059327376f * 1.4426950408889634f)

// ---------------- scratch ----------------
__device__ __align__(16) float g_q  [BB*NB*2*TT*2];
__device__ __align__(16) float g_kv [BB*NB*2*TT*4];
__device__ __align__(16) float g_o  [BB*TT*64];
__device__ __align__(16) float g_ab [BB*TT*64];
__device__ __align__(16) float g_cq [BB*CH*TT*8];
__device__ __align__(16) float g_ck [BB*CH*TT*8];
__device__ __align__(16) float g_cv [BB*CH*TT*8];
__device__ __align__(16) float g_entp[BB*TT*16];
__device__ __align__(16) float g_po [BB*CH*2*TT*8];   // partial o: [c][split2][t][8]
__device__ __align__(16) float g_pl [BB*CH*2*TT];     // partial l

__device__ __align__(16) float g_cwqkvT[64*192];
__device__ __align__(16) float g_cwoutT[64*64];
__device__ __align__(16) float g_fw1T[64*256];
__device__ __align__(16) float g_fw2T[256*64];

__device__ __forceinline__ float gelu_f(float x){
    return 0.5f * x * (1.0f + erff(x * 0.70710678118654752f));
}

#define K1_BLOCKS (BB*TT/4)   // 2048
#define TR_BLOCKS 48

// ---------------- K1: block extraction + tiny QKV (4 tok/block) + transpose tail ----------------
__global__ void __launch_bounds__(256) k1_blockqkv(const float* __restrict__ M,
                            const float* __restrict__ w,
                            const float* __restrict__ bias,
                            const float* __restrict__ cwqkv,
                            const float* __restrict__ cwout,
                            const float* __restrict__ fw1,
                            const float* __restrict__ fw2){
    int tid = threadIdx.x;
    if (blockIdx.x >= K1_BLOCKS){
        int stride = TR_BLOCKS * 256;
        int tid0 = (blockIdx.x - K1_BLOCKS) * 256 + tid;
        for (int idx = tid0; idx < 64*192; idx += stride){
            int j = idx / 192, o = idx - j*192;
            g_cwqkvT[idx] = cwqkv[o*64 + j];
        }
        for (int idx = tid0; idx < 64*64; idx += stride){
            int j = idx >> 6, o = idx & 63;
            g_cwoutT[idx] = cwout[o*64 + j];
        }
        for (int idx = tid0; idx < 64*256; idx += stride){
            int j = idx >> 8, o = idx & 255;
            g_fw1T[idx] = fw1[o*64 + j];
        }
        for (int idx = tid0; idx < 256*64; idx += stride){
            int j = idx >> 6, o = idx & 63;
            g_fw2T[idx] = fw2[o*256 + j];
        }
        return;
    }
    int bt0 = blockIdx.x * 4;
    int b = bt0 >> 9;
    __shared__ float mrow[256];
    mrow[tid] = M[bt0*64 + tid];
    __syncthreads();
    #pragma unroll
    for (int it = 0; it < 3; it++){
        int idx = tid + it*256;
        int tok = idx / 192, r = idx - tok*192;
        int t = (bt0 + tok) & 511;
        int n = r / 12, e = r - n*12;
        int br = n >> 2, bc = n & 3;
        int base = tok*64 + 16*br + 2*bc;
        float x0 = mrow[base], x1 = mrow[base+1], x2 = mrow[base+8], x3 = mrow[base+9];
        const float* wp = w + r*4;
        float val = bias[r] + wp[0]*x0 + wp[1]*x1 + wp[2]*x2 + wp[3]*x3;
        if (e < 4){
            int h = e >> 1, d = e & 1;
            g_q[(((b*NB+n)*2+h)*TT + t)*2 + d] = val * QS;
        } else if (e < 8){
            int ee = e - 4; int h = ee >> 1, d = ee & 1;
            g_kv[((b*NB+n)*2+h)*TT*4 + (t>>1)*8 + d*2 + (t&1)] = val;
        } else {
            int ee = e - 8; int h = ee >> 1, d = ee & 1;
            g_kv[((b*NB+n)*2+h)*TT*4 + (t>>1)*8 + 4 + d*2 + (t&1)] = val;
        }
    }
}

// ---------------- K2: 512 tiny attentions (d=2), paired ----------------
__global__ void __launch_bounds__(TT) k2_blockattn(){
    int c = blockIdx.x;                // 512
    __shared__ __align__(16) float sKV[TT*4];
    int t = threadIdx.x;
    ((float4*)sKV)[t] = ((const float4*)g_kv)[c*TT + t];
    __syncthreads();
    float2 q = ((const float2*)g_q)[c*TT + t];
    ull qxx = pk2(q.x, q.x), qyy = pk2(q.y, q.y);
    ull l2 = 0ull, oz2 = 0ull, ow2 = 0ull;
    const ulonglong2* s2 = (const ulonglong2*)sKV;
    #pragma unroll 8
    for (int p = 0; p < 256; p++){
        ulonglong2 kk = s2[p*2];
        ulonglong2 vv = s2[p*2+1];
        ull sc2 = mul2(qxx, kk.x);
        fma2(sc2, qyy, kk.y);
        float s0, s1; upk2(sc2, s0, s1);
        ull pp = pk2(ex2f(s0), ex2f(s1));
        add2(l2, pp);
        fma2(oz2, pp, vv.x);
        fma2(ow2, pp, vv.y);
    }
    float la, lb, za, zb, wa, wb;
    upk2(l2, la, lb); upk2(oz2, za, zb); upk2(ow2, wa, wb);
    float inv = __fdividef(1.f, la + lb);
    int b = c >> 5, n = (c >> 1) & 15, h = c & 1;
    ((float2*)g_o)[(b*TT + t)*32 + n*2 + h] = make_float2((za+zb)*inv, (wa+wb)*inv);
}

// ---------------- K4: block out-proj + cross QKV, 4 tok/block ----------------
__global__ void __launch_bounds__(192) k4_crossqkv(const float* __restrict__ bw,
                                                   const float* __restrict__ bb,
                                                   const float* __restrict__ bias){
    int bt0 = blockIdx.x * 4;
    int b = bt0 >> 9;
    int tid = threadIdx.x;
    __shared__ __align__(16) float s_xT[64*4];

    for (int idx = tid; idx < 256; idx += 192){
        int tok = idx >> 6, o = idx & 63;
        int n = o >> 2;
        float4 ov = ((const float4*)g_o)[(bt0+tok)*16 + n];
        float4 wv = ((const float4*)bw)[o];
        float acc = bb[o];
        acc = fmaf(wv.x, ov.x, acc); acc = fmaf(wv.y, ov.y, acc);
        acc = fmaf(wv.z, ov.z, acc); acc = fmaf(wv.w, ov.w, acc);
        s_xT[o*4 + tok] = acc;
        g_ab[(bt0+tok)*64 + o] = acc;
    }
    __syncthreads();

    float bs = bias[tid];
    ull acc0 = pk2(bs, bs), acc1 = pk2(bs, bs);
    #pragma unroll 8
    for (int j = 0; j < 64; j++){
        float w = g_cwqkvT[j*192 + tid];
        ull ww = pk2(w, w);
        ulonglong2 xx = *(const ulonglong2*)&s_xT[j*4];
        fma2(acc0, ww, xx.x); fma2(acc1, ww, xx.y);
    }
    float av[4];
    upk2(acc0, av[0], av[1]); upk2(acc1, av[2], av[3]);
    #pragma unroll
    for (int tok = 0; tok < 4; tok++){
        int t = (bt0 + tok) & 511;
        float v = av[tok];
        if (tid < 64){
            int h = tid >> 3, d = tid & 7;
            g_cq[((b*CH+h)*TT + t)*8 + d] = v * CS;
        } else if (tid < 128){
            int i = tid - 64; int h = i >> 3, d = i & 7;
            g_ck[(b*CH+h)*TT*8 + (t>>1)*16 + d*2 + (t&1)] = v;
        } else {
            int i = tid - 128; int h = i >> 3, d = i & 7;
            g_cv[(b*CH+h)*TT*8 + (t>>1)*16 + d*2 + (t&1)] = v;
        }
    }
}

// ---------------- K5: cross attention (d=8), 2-way s-split, split score chain ----------------
__global__ void __launch_bounds__(128) k5_crossattn(){
    int blk = blockIdx.x;              // 1024 = c(128) x sh(2) x tq(4)
    int c  = blk >> 3;
    int sh = (blk >> 2) & 1;
    int t  = (blk & 3)*128 + threadIdx.x;
    __shared__ __align__(16) float sK[256*8];
    __shared__ __align__(16) float sV[256*8];
    {
        const float4* kp = (const float4*)(g_ck + c*TT*8 + sh*2048);
        const float4* vp = (const float4*)(g_cv + c*TT*8 + sh*2048);
        for (int i = threadIdx.x; i < 512; i += 128){
            ((float4*)sK)[i] = kp[i];
            ((float4*)sV)[i] = vp[i];
        }
    }
    __syncthreads();
    ull qjj[8];
    {
        float4 qa = ((const float4*)g_cq)[(c*TT + t)*2];
        float4 qb = ((const float4*)g_cq)[(c*TT + t)*2 + 1];
        qjj[0]=pk2(qa.x,qa.x); qjj[1]=pk2(qa.y,qa.y); qjj[2]=pk2(qa.z,qa.z); qjj[3]=pk2(qa.w,qa.w);
        qjj[4]=pk2(qb.x,qb.x); qjj[5]=pk2(qb.y,qb.y); qjj[6]=pk2(qb.z,qb.z); qjj[7]=pk2(qb.w,qb.w);
    }
    ull l2 = 0ull;
    ull o2[8];
    #pragma unroll
    for (int j = 0; j < 8; j++) o2[j] = 0ull;
    const ulonglong2* kp2 = (const ulonglong2*)sK;
    const ulonglong2* vp2 = (const ulonglong2*)sV;
    #pragma unroll 4
    for (int p = 0; p < 128; p++){
        ulonglong2 k0 = kp2[p*4], k1 = kp2[p*4+1], k2v = kp2[p*4+2], k3 = kp2[p*4+3];
        // split score chain: two independent halves
        ull sca = mul2(qjj[0], k0.x);
        ull scb = mul2(qjj[4], k2v.x);
        fma2(sca, qjj[1], k0.y); fma2(scb, qjj[5], k2v.y);
        fma2(sca, qjj[2], k1.x); fma2(scb, qjj[6], k3.x);
        fma2(sca, qjj[3], k1.y); fma2(scb, qjj[7], k3.y);
        add2(sca, scb);
        float s0, s1; upk2(sca, s0, s1);
        ull pp = pk2(ex2f(s0), ex2f(s1));
        add2(l2, pp);
        ulonglong2 v0 = vp2[p*4], v1 = vp2[p*4+1], v2v = vp2[p*4+2], v3 = vp2[p*4+3];
        fma2(o2[0], pp, v0.x); fma2(o2[1], pp, v0.y);
        fma2(o2[2], pp, v1.x); fma2(o2[3], pp, v1.y);
        fma2(o2[4], pp, v2v.x); fma2(o2[5], pp, v2v.y);
        fma2(o2[6], pp, v3.x); fma2(o2[7], pp, v3.y);
    }
    float la, lb; upk2(l2, la, lb);
    int pidx = (c*2 + sh)*TT + t;
    g_pl[pidx] = la + lb;
    float ov[8];
    #pragma unroll
    for (int j = 0; j < 8; j++){
        float oa, ob; upk2(o2[j], oa, ob);
        ov[j] = oa + ob;
    }
    float4* pop = (float4*)(g_po + pidx*8);
    pop[0] = make_float4(ov[0], ov[1], ov[2], ov[3]);
    pop[1] = make_float4(ov[4], ov[5], ov[6], ov[7]);
}

// ---------------- K6: entropy by recompute (inv from partials; no k5b) ----------------
__global__ void __launch_bounds__(128) k6_entropy(){
    int blk = blockIdx.x;              // 1024 = b(16) * tile(4) * chunk(16)
    int b = blk >> 6;
    int tile = (blk >> 4) & 3;
    int chunk = blk & 15;
    int t = tile*128 + threadIdx.x;
    __shared__ __align__(16) float sK[8*256];
    for (int i = threadIdx.x; i < 512; i += 128){
        int h = i >> 6, f = i & 63;
        ((float4*)sK)[i] = ((const float4*)g_ck)[(b*CH+h)*1024 + chunk*64 + f];
    }
    __syncthreads();
    ull pm2[16];
    #pragma unroll
    for (int p = 0; p < 16; p++) pm2[p] = 0ull;
    #pragma unroll
    for (int h = 0; h < 8; h++){
        float4 qa = ((const float4*)g_cq)[((b*CH+h)*TT + t)*2];
        float4 qb = ((const float4*)g_cq)[((b*CH+h)*TT + t)*2 + 1];
        ull q0=pk2(qa.x,qa.x), q1=pk2(qa.y,qa.y), q2=pk2(qa.z,qa.z), q3=pk2(qa.w,qa.w);
        ull q4=pk2(qb.x,qb.x), q5=pk2(qb.y,qb.y), q6=pk2(qb.z,qb.z), q7=pk2(qb.w,qb.w);
        int c = b*CH + h;
        float l = g_pl[(c*2)*TT + t] + g_pl[(c*2+1)*TT + t];
        float il = __fdividef(1.f, l) * 0.125f;
        ull ivv = pk2(il, il);
        const ulonglong2* kh = (const ulonglong2*)(sK + h*256);
        #pragma unroll
        for (int p = 0; p < 16; p++){
            ulonglong2 k0 = kh[p*4], k1 = kh[p*4+1], k2v = kh[p*4+2], k3 = kh[p*4+3];
            ull sc2 = mul2(q0, k0.x);
            fma2(sc2, q1, k0.y); fma2(sc2, q2, k1.x); fma2(sc2, q3, k1.y);
            fma2(sc2, q4, k2v.x); fma2(sc2, q5, k2v.y);
            fma2(sc2, q6, k3.x); fma2(sc2, q7, k3.y);
            float s0, s1; upk2(sc2, s0, s1);
            ull pp = pk2(ex2f(s0), ex2f(s1));
            fma2(pm2[p], pp, ivv);
        }
    }
    float acc = 0.f;
    #pragma unroll
    for (int p = 0; p < 16; p++){
        float m0, m1; upk2(pm2[p], m0, m1);
        acc = fmaf(m0, __logf(m0 + 1e-9f), acc);
        acc = fmaf(m1, __logf(m1 + 1e-9f), acc);
    }
    g_entp[(b*TT + t)*16 + chunk] = acc;
}

// ---------------- K7: fused epilogue, 8 tok/block (combines k5 partials inline) ----------------
__global__ void __launch_bounds__(256) k7_fused(
    const float* __restrict__ M, const int* __restrict__ token_ids,
    const float* __restrict__ cbout,
    const float* __restrict__ g1, const float* __restrict__ be1,
    const float* __restrict__ fb1,
    const float* __restrict__ fb2,
    const float* __restrict__ g2, const float* __restrict__ be2,
    const float* __restrict__ sbase, const float* __restrict__ taff,
    const float* __restrict__ sw1, const float* __restrict__ sb1,
    const float* __restrict__ sw2, const float* __restrict__ sb2,
    float* __restrict__ out)
{
    int bt0 = blockIdx.x * 8;
    int b = bt0 >> 9;
    int tid = threadIdx.x;
    int lane = tid & 31, warp = tid >> 5;

    __shared__ __align__(16) float s_coT[64*8];
    __shared__ __align__(16) float s_abT[64*8];
    __shared__ __align__(16) float s_yT [64*8];
    __shared__ __align__(16) float s_xT [64*8];
    __shared__ __align__(16) float s_x2T[64*8];
    __shared__ __align__(16) float s_h1T[256*8];
    __shared__ __align__(16) float s_fp [4*64*8];
    __shared__ float s_inv[64];        // [tok][h]
    __shared__ float s_mu[8], s_rs[8];
    __shared__ float s_ent[8];
    __shared__ float s_hs[8*32];
    __shared__ float s_sens[8*16];

    if (tid < 64){
        int tok = tid >> 3, h = tid & 7;
        int c = b*CH + h;
        int t = (bt0 + tok) & 511;
        float l = g_pl[(c*2)*TT + t] + g_pl[(c*2+1)*TT + t];
        s_inv[tid] = __fdividef(1.f, l);
    }
    __syncthreads();

    for (int idx = tid; idx < 512; idx += 256){
        int tok = idx >> 6, o = idx & 63;
        int h = o >> 3, d = o & 7;
        int c = b*CH + h;
        int t = (bt0 + tok) & 511;
        int base0 = ((c*2)*TT + t)*8 + d;
        float po = g_po[base0] + g_po[base0 + TT*8];
        s_coT[o*8 + tok] = po * s_inv[tok*8 + h];
        s_abT[o*8 + tok] = g_ab[(bt0+tok)*64 + o];
    }
    __syncthreads();

    int o64 = tid & 63, qr = tid >> 6;

    // cross out-proj (j split 4-ways, packed)
    {
        ull acc[4] = {0ull, 0ull, 0ull, 0ull};
        int j0 = qr*16;
        #pragma unroll
        for (int j = j0; j < j0+16; j++){
            float w = g_cwoutT[j*64 + o64];
            ull ww = pk2(w, w);
            const ull* cp = (const ull*)&s_coT[j*8];
            fma2(acc[0], ww, cp[0]); fma2(acc[1], ww, cp[1]);
            fma2(acc[2], ww, cp[2]); fma2(acc[3], ww, cp[3]);
        }
        ull* fp = (ull*)&s_fp[qr*512 + o64*8];
        fp[0]=acc[0]; fp[1]=acc[1]; fp[2]=acc[2]; fp[3]=acc[3];
    }
    __syncthreads();
    for (int idx = tid; idx < 512; idx += 256){
        int o = idx >> 3, tok = idx & 7;
        s_yT[o*8 + tok] = cbout[o] + s_abT[o*8+tok]
                + s_fp[o*8+tok] + s_fp[512 + o*8+tok]
                + s_fp[1024 + o*8+tok] + s_fp[1536 + o*8+tok];
    }
    __syncthreads();

    // LN1 stats
    {
        float v0 = s_yT[lane*8 + warp];
        float v1 = s_yT[(lane+32)*8 + warp];
        float sv = v0 + v1, sq = v0*v0 + v1*v1;
        #pragma unroll
        for (int off = 16; off > 0; off >>= 1){
            sv += __shfl_down_sync(0xffffffffu, sv, off);
            sq += __shfl_down_sync(0xffffffffu, sq, off);
        }
        if (lane == 0){
            float mean = sv * (1.f/64.f);
            float var  = sq * (1.f/64.f) - mean*mean;
            s_mu[warp] = mean;
            s_rs[warp] = rsqrtf(var + 1e-5f);
        }
    }
    __syncthreads();
    for (int idx = tid; idx < 512; idx += 256){
        int o = idx >> 3, tok = idx & 7;
        s_xT[o*8+tok] = (s_yT[o*8+tok] - s_mu[tok]) * s_rs[tok] * g1[o] + be1[o];
    }
    __syncthreads();

    // FFN1 (packed)
    {
        float bs = fb1[tid];
        ull acc[4];
        #pragma unroll
        for (int k = 0; k < 4; k++) acc[k] = pk2(bs, bs);
        #pragma unroll 8
        for (int j = 0; j < 64; j++){
            float w = g_fw1T[j*256 + tid];
            ull ww = pk2(w, w);
            const ulonglong2* xp = (const ulonglong2*)&s_xT[j*8];
            ulonglong2 x0 = xp[0], x1 = xp[1];
            fma2(acc[0], ww, x0.x); fma2(acc[1], ww, x0.y);
            fma2(acc[2], ww, x1.x); fma2(acc[3], ww, x1.y);
        }
        ull* hp = (ull*)&s_h1T[tid*8];
        #pragma unroll
        for (int k = 0; k < 4; k++){
            float a, bvl; upk2(acc[k], a, bvl);
            hp[k] = pk2(gelu_f(a), gelu_f(bvl));
        }
    }
    __syncthreads();

    // FFN2 (j split 4-ways, packed)
    {
        ull acc[4] = {0ull, 0ull, 0ull, 0ull};
        int j0 = qr*64;
        #pragma unroll 8
        for (int j = j0; j < j0+64; j++){
            float w = g_fw2T[j*64 + o64];
            ull ww = pk2(w, w);
            const ull* hp = (const ull*)&s_h1T[j*8];
            fma2(acc[0], ww, hp[0]); fma2(acc[1], ww, hp[1]);
            fma2(acc[2], ww, hp[2]); fma2(acc[3], ww, hp[3]);
        }
        ull* fp = (ull*)&s_fp[qr*512 + o64*8];
        fp[0]=acc[0]; fp[1]=acc[1]; fp[2]=acc[2]; fp[3]=acc[3];
    }
    __syncthreads();
    for (int idx = tid; idx < 512; idx += 256){
        int o = idx >> 3, tok = idx & 7;
        s_yT[o*8 + tok] = s_xT[o*8+tok] + fb2[o]
                + s_fp[o*8+tok] + s_fp[512 + o*8+tok]
                + s_fp[1024 + o*8+tok] + s_fp[1536 + o*8+tok];
    }
    __syncthreads();

    // LN2 stats
    {
        float v0 = s_yT[lane*8 + warp];
        float v1 = s_yT[(lane+32)*8 + warp];
        float sv = v0 + v1, sq = v0*v0 + v1*v1;
        #pragma unroll
        for (int off = 16; off > 0; off >>= 1){
            sv += __shfl_down_sync(0xffffffffu, sv, off);
            sq += __shfl_down_sync(0xffffffffu, sq, off);
        }
        if (lane == 0){
            float mean = sv * (1.f/64.f);
            float var  = sq * (1.f/64.f) - mean*mean;
            s_mu[warp] = mean;
            s_rs[warp] = rsqrtf(var + 1e-5f);
        }
    }
    __syncthreads();
    for (int idx = tid; idx < 512; idx += 256){
        int o = idx >> 3, tok = idx & 7;
        s_x2T[o*8+tok] = (s_yT[o*8+tok] - s_mu[tok]) * s_rs[tok] * g2[o] + be2[o];
    }
    if (tid < 8){
        float e = 0.f;
        #pragma unroll
        for (int c = 0; c < 16; c++) e += g_entp[(bt0+tid)*16 + c];
        s_ent[tid] = -e;
    }
    __syncthreads();

    // sensitivity MLP
    {
        int tok = tid >> 5, hh = tid & 31;
        int tk = token_ids[bt0 + tok];
        float acc = sb1[hh];
        const float* wp = sw1 + hh*17;
        const float* ap = taff + (size_t)tk*16;
        #pragma unroll
        for (int a = 0; a < 16; a++) acc = fmaf(wp[a], ap[a], acc);
        acc = fmaf(wp[16], s_ent[tok], acc);
        s_hs[tok*32 + hh] = gelu_f(acc);
    }
    __syncthreads();
    if (tid < 128){
        int tok = tid >> 4, oo = tid & 15;
        float acc = sb2[oo];
        const float* wp = sw2 + oo*32;
        #pragma unroll
        for (int j = 0; j < 32; j++) acc = fmaf(wp[j], s_hs[tok*32 + j], acc);
        s_sens[tok*16 + oo] = sbase[oo] / (1.f + __expf(-acc));
    }
    __syncthreads();

    for (int idx = tid; idx < 512; idx += 256){
        int tok = idx >> 6, o = idx & 63;
        float m = M[(bt0+tok)*64 + o];
        out[(bt0+tok)*64 + o] = fmaf(s_x2T[o*8+tok] - m, s_sens[tok*16 + (o>>2)], m);
    }
}

// ---------------- launch ----------------
extern "C" void kernel_launch(void* const* d_in, const int* in_sizes, int n_in,
                              void* d_out, int out_size){
    const float* M     = (const float*)d_in[0];
    const int*   tok   = (const int*)  d_in[1];
    const float* bwqkv = (const float*)d_in[2];
    const float* bbqkv = (const float*)d_in[3];
    const float* bwout = (const float*)d_in[4];
    const float* bbout = (const float*)d_in[5];
    const float* cwqkv = (const float*)d_in[6];
    const float* cbqkv = (const float*)d_in[7];
    const float* cwout = (const float*)d_in[8];
    const float* cbout = (const float*)d_in[9];
    const float* g1    = (const float*)d_in[10];
    const float* b1    = (const float*)d_in[11];
    const float* fw1   = (const float*)d_in[12];
    const float* fb1   = (const float*)d_in[13];
    const float* fw2   = (const float*)d_in[14];
    const float* fb2   = (const float*)d_in[15];
    const float* g2    = (const float*)d_in[16];
    const float* b2    = (const float*)d_in[17];
    const float* sbase = (const float*)d_in[18];
    const float* taff  = (const float*)d_in[19];
    const float* sw1   = (const float*)d_in[20];
    const float* sb1   = (const float*)d_in[21];
    const float* sw2   = (const float*)d_in[22];
    const float* sb2   = (const float*)d_in[23];

    k1_blockqkv<<<K1_BLOCKS + TR_BLOCKS, 256>>>(M, bwqkv, bbqkv, cwqkv, cwout, fw1, fw2);
    k2_blockattn<<<512, TT>>>();
    k4_crossqkv<<<BB*TT/4, 192>>>(bwout, bbout, cbqkv);
    k5_crossattn<<<1024, 128>>>();
    k6_entropy<<<1024, 128>>>();
    k7_fused<<<BB*TT/8, 256>>>(M, tok, cbout, g1, b1, fb1, fb2, g2, b2,
                               sbase, taff, sw1, sb1, sw2, sb2, (float*)d_out);
}

// round 17
// speedup vs baseline: 1.0146x; 1.0026x over previous
#include <cuda_runtime.h>
#include <cstdint>

#define BB 16
#define TT 512
#define NB 16
#define CH 8

typedef unsigned long long ull;

// ---------------- packed f32x2 helpers ----------------
__device__ __forceinline__ ull pk2(float a, float b){
    ull r; asm("mov.b64 %0, {%1,%2};" : "=l"(r) : "f"(a), "f"(b)); return r; }
__device__ __forceinline__ void upk2(ull v, float& a, float& b){
    asm("mov.b64 {%0,%1}, %2;" : "=f"(a), "=f"(b) : "l"(v)); }
__device__ __forceinline__ void fma2(ull& d, ull a, ull b){
    asm("fma.rn.f32x2 %0, %1, %2, %0;" : "+l"(d) : "l"(a), "l"(b)); }
__device__ __forceinline__ ull mul2(ull a, ull b){
    ull r; asm("mul.rn.f32x2 %0, %1, %2;" : "=l"(r) : "l"(a), "l"(b)); return r; }
__device__ __forceinline__ void add2(ull& d, ull a){
    asm("add.rn.f32x2 %0, %0, %1;" : "+l"(d) : "l"(a)); }
__device__ __forceinline__ float ex2f(float x){
    float r; asm("ex2.approx.f32 %0, %1;" : "=f"(r) : "f"(x)); return r; }

#define QS  (0.70710678118654752f * 1.4426950408889634f)
#define CS  (0.35355339059327376f * 1.4426950408889634f)

// ---------------- scratch ----------------
__device__ __align__(16) float g_q  [BB*NB*2*TT*2];
__device__ __align__(16) float g_kv [BB*NB*2*TT*4];
__device__ __align__(16) float g_o  [BB*TT*64];
__device__ __align__(16) float g_ab [BB*TT*64];
__device__ __align__(16) float g_cq [BB*CH*TT*8];
__device__ __align__(16) float g_ck [BB*CH*TT*8];
__device__ __align__(16) float g_cv [BB*CH*TT*8];
__device__ __align__(16) float g_entp[BB*TT*16];
__device__ __align__(16) float g_po [BB*CH*2*TT*8];   // partial o: [c][split2][t][8]
__device__ __align__(16) float g_pl [BB*CH*2*TT];     // partial l

__device__ __align__(16) float g_cwqkvT[64*192];
__device__ __align__(16) float g_cwoutT[64*64];
__device__ __align__(16) float g_fw1T[64*256];
__device__ __align__(16) float g_fw2T[256*64];

__device__ __forceinline__ float gelu_f(float x){
    return 0.5f * x * (1.0f + erff(x * 0.70710678118654752f));
}

#define K1_BLOCKS (BB*TT/4)   // 2048
#define TR_BLOCKS 48

// ---------------- K1: block extraction + tiny QKV (4 tok/block) + transpose tail ----------------
__global__ void __launch_bounds__(256) k1_blockqkv(const float* __restrict__ M,
                            const float* __restrict__ w,
                            const float* __restrict__ bias,
                            const float* __restrict__ cwqkv,
                            const float* __restrict__ cwout,
                            const float* __restrict__ fw1,
                            const float* __restrict__ fw2){
    int tid = threadIdx.x;
    if (blockIdx.x >= K1_BLOCKS){
        int stride = TR_BLOCKS * 256;
        int tid0 = (blockIdx.x - K1_BLOCKS) * 256 + tid;
        for (int idx = tid0; idx < 64*192; idx += stride){
            int j = idx / 192, o = idx - j*192;
            g_cwqkvT[idx] = cwqkv[o*64 + j];
        }
        for (int idx = tid0; idx < 64*64; idx += stride){
            int j = idx >> 6, o = idx & 63;
            g_cwoutT[idx] = cwout[o*64 + j];
        }
        for (int idx = tid0; idx < 64*256; idx += stride){
            int j = idx >> 8, o = idx & 255;
            g_fw1T[idx] = fw1[o*64 + j];
        }
        for (int idx = tid0; idx < 256*64; idx += stride){
            int j = idx >> 6, o = idx & 63;
            g_fw2T[idx] = fw2[o*256 + j];
        }
        return;
    }
    int bt0 = blockIdx.x * 4;
    int b = bt0 >> 9;
    __shared__ float mrow[256];
    mrow[tid] = M[bt0*64 + tid];
    __syncthreads();
    #pragma unroll
    for (int it = 0; it < 3; it++){
        int idx = tid + it*256;
        int tok = idx / 192, r = idx - tok*192;
        int t = (bt0 + tok) & 511;
        int n = r / 12, e = r - n*12;
        int br = n >> 2, bc = n & 3;
        int base = tok*64 + 16*br + 2*bc;
        float x0 = mrow[base], x1 = mrow[base+1], x2 = mrow[base+8], x3 = mrow[base+9];
        const float* wp = w + r*4;
        float val = bias[r] + wp[0]*x0 + wp[1]*x1 + wp[2]*x2 + wp[3]*x3;
        if (e < 4){
            int h = e >> 1, d = e & 1;
            g_q[(((b*NB+n)*2+h)*TT + t)*2 + d] = val * QS;
        } else if (e < 8){
            int ee = e - 4; int h = ee >> 1, d = ee & 1;
            g_kv[((b*NB+n)*2+h)*TT*4 + (t>>1)*8 + d*2 + (t&1)] = val;
        } else {
            int ee = e - 8; int h = ee >> 1, d = ee & 1;
            g_kv[((b*NB+n)*2+h)*TT*4 + (t>>1)*8 + 4 + d*2 + (t&1)] = val;
        }
    }
}

// ---------------- K2: 512 tiny attentions (d=2), paired ----------------
__global__ void __launch_bounds__(TT) k2_blockattn(){
    int c = blockIdx.x;                // 512
    __shared__ __align__(16) float sKV[TT*4];
    int t = threadIdx.x;
    ((float4*)sKV)[t] = ((const float4*)g_kv)[c*TT + t];
    __syncthreads();
    float2 q = ((const float2*)g_q)[c*TT + t];
    ull qxx = pk2(q.x, q.x), qyy = pk2(q.y, q.y);
    ull l2 = 0ull, oz2 = 0ull, ow2 = 0ull;
    const ulonglong2* s2 = (const ulonglong2*)sKV;
    #pragma unroll 8
    for (int p = 0; p < 256; p++){
        ulonglong2 kk = s2[p*2];
        ulonglong2 vv = s2[p*2+1];
        ull sc2 = mul2(qxx, kk.x);
        fma2(sc2, qyy, kk.y);
        float s0, s1; upk2(sc2, s0, s1);
        ull pp = pk2(ex2f(s0), ex2f(s1));
        add2(l2, pp);
        fma2(oz2, pp, vv.x);
        fma2(ow2, pp, vv.y);
    }
    float la, lb, za, zb, wa, wb;
    upk2(l2, la, lb); upk2(oz2, za, zb); upk2(ow2, wa, wb);
    float inv = __fdividef(1.f, la + lb);
    int b = c >> 5, n = (c >> 1) & 15, h = c & 1;
    ((float2*)g_o)[(b*TT + t)*32 + n*2 + h] = make_float2((za+zb)*inv, (wa+wb)*inv);
}

// ---------------- K4: block out-proj + cross QKV, 4 tok/block ----------------
__global__ void __launch_bounds__(192) k4_crossqkv(const float* __restrict__ bw,
                                                   const float* __restrict__ bb,
                                                   const float* __restrict__ bias){
    int bt0 = blockIdx.x * 4;
    int b = bt0 >> 9;
    int tid = threadIdx.x;
    __shared__ __align__(16) float s_xT[64*4];

    for (int idx = tid; idx < 256; idx += 192){
        int tok = idx >> 6, o = idx & 63;
        int n = o >> 2;
        float4 ov = ((const float4*)g_o)[(bt0+tok)*16 + n];
        float4 wv = ((const float4*)bw)[o];
        float acc = bb[o];
        acc = fmaf(wv.x, ov.x, acc); acc = fmaf(wv.y, ov.y, acc);
        acc = fmaf(wv.z, ov.z, acc); acc = fmaf(wv.w, ov.w, acc);
        s_xT[o*4 + tok] = acc;
        g_ab[(bt0+tok)*64 + o] = acc;
    }
    __syncthreads();

    float bs = bias[tid];
    ull acc0 = pk2(bs, bs), acc1 = pk2(bs, bs);
    #pragma unroll 8
    for (int j = 0; j < 64; j++){
        float w = g_cwqkvT[j*192 + tid];
        ull ww = pk2(w, w);
        ulonglong2 xx = *(const ulonglong2*)&s_xT[j*4];
        fma2(acc0, ww, xx.x); fma2(acc1, ww, xx.y);
    }
    float av[4];
    upk2(acc0, av[0], av[1]); upk2(acc1, av[2], av[3]);
    #pragma unroll
    for (int tok = 0; tok < 4; tok++){
        int t = (bt0 + tok) & 511;
        float v = av[tok];
        if (tid < 64){
            int h = tid >> 3, d = tid & 7;
            g_cq[((b*CH+h)*TT + t)*8 + d] = v * CS;
        } else if (tid < 128){
            int i = tid - 64; int h = i >> 3, d = i & 7;
            g_ck[(b*CH+h)*TT*8 + (t>>1)*16 + d*2 + (t&1)] = v;
        } else {
            int i = tid - 128; int h = i >> 3, d = i & 7;
            g_cv[(b*CH+h)*TT*8 + (t>>1)*16 + d*2 + (t&1)] = v;
        }
    }
}

// ---------------- K5: cross attention (d=8), 2-way s-split, split score chain ----------------
__global__ void __launch_bounds__(128) k5_crossattn(){
    int blk = blockIdx.x;              // 1024 = c(128) x sh(2) x tq(4)
    int c  = blk >> 3;
    int sh = (blk >> 2) & 1;
    int t  = (blk & 3)*128 + threadIdx.x;
    __shared__ __align__(16) float sK[256*8];
    __shared__ __align__(16) float sV[256*8];
    {
        const float4* kp = (const float4*)(g_ck + c*TT*8 + sh*2048);
        const float4* vp = (const float4*)(g_cv + c*TT*8 + sh*2048);
        for (int i = threadIdx.x; i < 512; i += 128){
            ((float4*)sK)[i] = kp[i];
            ((float4*)sV)[i] = vp[i];
        }
    }
    __syncthreads();
    ull qjj[8];
    {
        float4 qa = ((const float4*)g_cq)[(c*TT + t)*2];
        float4 qb = ((const float4*)g_cq)[(c*TT + t)*2 + 1];
        qjj[0]=pk2(qa.x,qa.x); qjj[1]=pk2(qa.y,qa.y); qjj[2]=pk2(qa.z,qa.z); qjj[3]=pk2(qa.w,qa.w);
        qjj[4]=pk2(qb.x,qb.x); qjj[5]=pk2(qb.y,qb.y); qjj[6]=pk2(qb.z,qb.z); qjj[7]=pk2(qb.w,qb.w);
    }
    ull l2 = 0ull;
    ull o2[8];
    #pragma unroll
    for (int j = 0; j < 8; j++) o2[j] = 0ull;
    const ulonglong2* kp2 = (const ulonglong2*)sK;
    const ulonglong2* vp2 = (const ulonglong2*)sV;
    #pragma unroll 4
    for (int p = 0; p < 128; p++){
        ulonglong2 k0 = kp2[p*4], k1 = kp2[p*4+1], k2v = kp2[p*4+2], k3 = kp2[p*4+3];
        ull sca = mul2(qjj[0], k0.x);
        ull scb = mul2(qjj[4], k2v.x);
        fma2(sca, qjj[1], k0.y); fma2(scb, qjj[5], k2v.y);
        fma2(sca, qjj[2], k1.x); fma2(scb, qjj[6], k3.x);
        fma2(sca, qjj[3], k1.y); fma2(scb, qjj[7], k3.y);
        add2(sca, scb);
        float s0, s1; upk2(sca, s0, s1);
        ull pp = pk2(ex2f(s0), ex2f(s1));
        add2(l2, pp);
        ulonglong2 v0 = vp2[p*4], v1 = vp2[p*4+1], v2v = vp2[p*4+2], v3 = vp2[p*4+3];
        fma2(o2[0], pp, v0.x); fma2(o2[1], pp, v0.y);
        fma2(o2[2], pp, v1.x); fma2(o2[3], pp, v1.y);
        fma2(o2[4], pp, v2v.x); fma2(o2[5], pp, v2v.y);
        fma2(o2[6], pp, v3.x); fma2(o2[7], pp, v3.y);
    }
    float la, lb; upk2(l2, la, lb);
    int pidx = (c*2 + sh)*TT + t;
    g_pl[pidx] = la + lb;
    float ov[8];
    #pragma unroll
    for (int j = 0; j < 8; j++){
        float oa, ob; upk2(o2[j], oa, ob);
        ov[j] = oa + ob;
    }
    float4* pop = (float4*)(g_po + pidx*8);
    pop[0] = make_float4(ov[0], ov[1], ov[2], ov[3]);
    pop[1] = make_float4(ov[4], ov[5], ov[6], ov[7]);
}

// ---------------- K6: entropy by recompute (inv from partials; no k5b) ----------------
__global__ void __launch_bounds__(128) k6_entropy(){
    int blk = blockIdx.x;              // 1024 = b(16) * tile(4) * chunk(16)
    int b = blk >> 6;
    int tile = (blk >> 4) & 3;
    int chunk = blk & 15;
    int t = tile*128 + threadIdx.x;
    __shared__ __align__(16) float sK[8*256];
    for (int i = threadIdx.x; i < 512; i += 128){
        int h = i >> 6, f = i & 63;
        ((float4*)sK)[i] = ((const float4*)g_ck)[(b*CH+h)*1024 + chunk*64 + f];
    }
    __syncthreads();
    ull pm2[16];
    #pragma unroll
    for (int p = 0; p < 16; p++) pm2[p] = 0ull;
    #pragma unroll
    for (int h = 0; h < 8; h++){
        float4 qa = ((const float4*)g_cq)[((b*CH+h)*TT + t)*2];
        float4 qb = ((const float4*)g_cq)[((b*CH+h)*TT + t)*2 + 1];
        ull q0=pk2(qa.x,qa.x), q1=pk2(qa.y,qa.y), q2=pk2(qa.z,qa.z), q3=pk2(qa.w,qa.w);
        ull q4=pk2(qb.x,qb.x), q5=pk2(qb.y,qb.y), q6=pk2(qb.z,qb.z), q7=pk2(qb.w,qb.w);
        int c = b*CH + h;
        float l = g_pl[(c*2)*TT + t] + g_pl[(c*2+1)*TT + t];
        float il = __fdividef(1.f, l) * 0.125f;
        ull ivv = pk2(il, il);
        const ulonglong2* kh = (const ulonglong2*)(sK + h*256);
        #pragma unroll
        for (int p = 0; p < 16; p++){
            ulonglong2 k0 = kh[p*4], k1 = kh[p*4+1], k2v = kh[p*4+2], k3 = kh[p*4+3];
            ull sc2 = mul2(q0, k0.x);
            fma2(sc2, q1, k0.y); fma2(sc2, q2, k1.x); fma2(sc2, q3, k1.y);
            fma2(sc2, q4, k2v.x); fma2(sc2, q5, k2v.y);
            fma2(sc2, q6, k3.x); fma2(sc2, q7, k3.y);
            float s0, s1; upk2(sc2, s0, s1);
            ull pp = pk2(ex2f(s0), ex2f(s1));
            fma2(pm2[p], pp, ivv);
        }
    }
    float acc = 0.f;
    #pragma unroll
    for (int p = 0; p < 16; p++){
        float m0, m1; upk2(pm2[p], m0, m1);
        acc = fmaf(m0, __logf(m0 + 1e-9f), acc);
        acc = fmaf(m1, __logf(m1 + 1e-9f), acc);
    }
    g_entp[(b*TT + t)*16 + chunk] = acc;
}

// ---------------- K7: fused epilogue, 8 tok/block (combines k5 partials inline) ----------------
__global__ void __launch_bounds__(256) k7_fused(
    const float* __restrict__ M, const int* __restrict__ token_ids,
    const float* __restrict__ cbout,
    const float* __restrict__ g1, const float* __restrict__ be1,
    const float* __restrict__ fb1,
    const float* __restrict__ fb2,
    const float* __restrict__ g2, const float* __restrict__ be2,
    const float* __restrict__ sbase, const float* __restrict__ taff,
    const float* __restrict__ sw1, const float* __restrict__ sb1,
    const float* __restrict__ sw2, const float* __restrict__ sb2,
    float* __restrict__ out)
{
    int bt0 = blockIdx.x * 8;
    int b = bt0 >> 9;
    int tid = threadIdx.x;
    int lane = tid & 31, warp = tid >> 5;

    __shared__ __align__(16) float s_coT[64*8];
    __shared__ __align__(16) float s_abT[64*8];
    __shared__ __align__(16) float s_yT [64*8];
    __shared__ __align__(16) float s_xT [64*8];
    __shared__ __align__(16) float s_x2T[64*8];
    __shared__ __align__(16) float s_h1T[256*8];
    __shared__ __align__(16) float s_fp [4*64*8];
    __shared__ float s_inv[64];        // [tok][h]
    __shared__ float s_mu[8], s_rs[8];
    __shared__ float s_ent[8];
    __shared__ float s_hs[8*32];
    __shared__ float s_sens[8*16];

    if (tid < 64){
        int tok = tid >> 3, h = tid & 7;
        int c = b*CH + h;
        int t = (bt0 + tok) & 511;
        float l = g_pl[(c*2)*TT + t] + g_pl[(c*2+1)*TT + t];
        s_inv[tid] = __fdividef(1.f, l);
    }
    __syncthreads();

    for (int idx = tid; idx < 512; idx += 256){
        int tok = idx >> 6, o = idx & 63;
        int h = o >> 3, d = o & 7;
        int c = b*CH + h;
        int t = (bt0 + tok) & 511;
        int base0 = ((c*2)*TT + t)*8 + d;
        float po = g_po[base0] + g_po[base0 + TT*8];
        s_coT[o*8 + tok] = po * s_inv[tok*8 + h];
        s_abT[o*8 + tok] = g_ab[(bt0+tok)*64 + o];
    }
    __syncthreads();

    int o64 = tid & 63, qr = tid >> 6;

    // cross out-proj (j split 4-ways, packed)
    {
        ull acc[4] = {0ull, 0ull, 0ull, 0ull};
        int j0 = qr*16;
        #pragma unroll
        for (int j = j0; j < j0+16; j++){
            float w = g_cwoutT[j*64 + o64];
            ull ww = pk2(w, w);
            const ull* cp = (const ull*)&s_coT[j*8];
            fma2(acc[0], ww, cp[0]); fma2(acc[1], ww, cp[1]);
            fma2(acc[2], ww, cp[2]); fma2(acc[3], ww, cp[3]);
        }
        ull* fp = (ull*)&s_fp[qr*512 + o64*8];
        fp[0]=acc[0]; fp[1]=acc[1]; fp[2]=acc[2]; fp[3]=acc[3];
    }
    __syncthreads();
    for (int idx = tid; idx < 512; idx += 256){
        int o = idx >> 3, tok = idx & 7;
        s_yT[o*8 + tok] = cbout[o] + s_abT[o*8+tok]
                + s_fp[o*8+tok] + s_fp[512 + o*8+tok]
                + s_fp[1024 + o*8+tok] + s_fp[1536 + o*8+tok];
    }
    __syncthreads();

    // LN1 stats
    {
        float v0 = s_yT[lane*8 + warp];
        float v1 = s_yT[(lane+32)*8 + warp];
        float sv = v0 + v1, sq = v0*v0 + v1*v1;
        #pragma unroll
        for (int off = 16; off > 0; off >>= 1){
            sv += __shfl_down_sync(0xffffffffu, sv, off);
            sq += __shfl_down_sync(0xffffffffu, sq, off);
        }
        if (lane == 0){
            float mean = sv * (1.f/64.f);
            float var  = sq * (1.f/64.f) - mean*mean;
            s_mu[warp] = mean;
            s_rs[warp] = rsqrtf(var + 1e-5f);
        }
    }
    __syncthreads();
    for (int idx = tid; idx < 512; idx += 256){
        int o = idx >> 3, tok = idx & 7;
        s_xT[o*8+tok] = (s_yT[o*8+tok] - s_mu[tok]) * s_rs[tok] * g1[o] + be1[o];
    }
    __syncthreads();

    // FFN1 (packed)
    {
        float bs = fb1[tid];
        ull acc[4];
        #pragma unroll
        for (int k = 0; k < 4; k++) acc[k] = pk2(bs, bs);
        #pragma unroll 8
        for (int j = 0; j < 64; j++){
            float w = g_fw1T[j*256 + tid];
            ull ww = pk2(w, w);
            const ulonglong2* xp = (const ulonglong2*)&s_xT[j*8];
            ulonglong2 x0 = xp[0], x1 = xp[1];
            fma2(acc[0], ww, x0.x); fma2(acc[1], ww, x0.y);
            fma2(acc[2], ww, x1.x); fma2(acc[3], ww, x1.y);
        }
        ull* hp = (ull*)&s_h1T[tid*8];
        #pragma unroll
        for (int k = 0; k < 4; k++){
            float a, bvl; upk2(acc[k], a, bvl);
            hp[k] = pk2(gelu_f(a), gelu_f(bvl));
        }
    }
    __syncthreads();

    // FFN2 (j split 4-ways, packed)
    {
        ull acc[4] = {0ull, 0ull, 0ull, 0ull};
        int j0 = qr*64;
        #pragma unroll 8
        for (int j = j0; j < j0+64; j++){
            float w = g_fw2T[j*64 + o64];
            ull ww = pk2(w, w);
            const ull* hp = (const ull*)&s_h1T[j*8];
            fma2(acc[0], ww, hp[0]); fma2(acc[1], ww, hp[1]);
            fma2(acc[2], ww, hp[2]); fma2(acc[3], ww, hp[3]);
        }
        ull* fp = (ull*)&s_fp[qr*512 + o64*8];
        fp[0]=acc[0]; fp[1]=acc[1]; fp[2]=acc[2]; fp[3]=acc[3];
    }
    __syncthreads();
    for (int idx = tid; idx < 512; idx += 256){
        int o = idx >> 3, tok = idx & 7;
        s_yT[o*8 + tok] = s_xT[o*8+tok] + fb2[o]
                + s_fp[o*8+tok] + s_fp[512 + o*8+tok]
                + s_fp[1024 + o*8+tok] + s_fp[1536 + o*8+tok];
    }
    __syncthreads();

    // LN2 stats
    {
        float v0 = s_yT[lane*8 + warp];
        float v1 = s_yT[(lane+32)*8 + warp];
        float sv = v0 + v1, sq = v0*v0 + v1*v1;
        #pragma unroll
        for (int off = 16; off > 0; off >>= 1){
            sv += __shfl_down_sync(0xffffffffu, sv, off);
            sq += __shfl_down_sync(0xffffffffu, sq, off);
        }
        if (lane == 0){
            float mean = sv * (1.f/64.f);
            float var  = sq * (1.f/64.f) - mean*mean;
            s_mu[warp] = mean;
            s_rs[warp] = rsqrtf(var + 1e-5f);
        }
    }
    __syncthreads();
    for (int idx = tid; idx < 512; idx += 256){
        int o = idx >> 3, tok = idx & 7;
        s_x2T[o*8+tok] = (s_yT[o*8+tok] - s_mu[tok]) * s_rs[tok] * g2[o] + be2[o];
    }
    if (tid < 8){
        float e = 0.f;
        #pragma unroll
        for (int c = 0; c < 16; c++) e += g_entp[(bt0+tid)*16 + c];
        s_ent[tid] = -e;
    }
    __syncthreads();

    // sensitivity MLP
    {
        int tok = tid >> 5, hh = tid & 31;
        int tk = token_ids[bt0 + tok];
        float acc = sb1[hh];
        const float* wp = sw1 + hh*17;
        const float* ap = taff + (size_t)tk*16;
        #pragma unroll
        for (int a = 0; a < 16; a++) acc = fmaf(wp[a], ap[a], acc);
        acc = fmaf(wp[16], s_ent[tok], acc);
        s_hs[tok*32 + hh] = gelu_f(acc);
    }
    __syncthreads();
    if (tid < 128){
        int tok = tid >> 4, oo = tid & 15;
        float acc = sb2[oo];
        const float* wp = sw2 + oo*32;
        #pragma unroll
        for (int j = 0; j < 32; j++) acc = fmaf(wp[j], s_hs[tok*32 + j], acc);
        s_sens[tok*16 + oo] = sbase[oo] / (1.f + __expf(-acc));
    }
    __syncthreads();

    for (int idx = tid; idx < 512; idx += 256){
        int tok = idx >> 6, o = idx & 63;
        float m = M[(bt0+tok)*64 + o];
        out[(bt0+tok)*64 + o] = fmaf(s_x2T[o*8+tok] - m, s_sens[tok*16 + (o>>2)], m);
    }
}

// ---------------- launch ----------------
extern "C" void kernel_launch(void* const* d_in, const int* in_sizes, int n_in,
                              void* d_out, int out_size){
    const float* M     = (const float*)d_in[0];
    const int*   tok   = (const int*)  d_in[1];
    const float* bwqkv = (const float*)d_in[2];
    const float* bbqkv = (const float*)d_in[3];
    const float* bwout = (const float*)d_in[4];
    const float* bbout = (const float*)d_in[5];
    const float* cwqkv = (const float*)d_in[6];
    const float* cbqkv = (const float*)d_in[7];
    const float* cwout = (const float*)d_in[8];
    const float* cbout = (const float*)d_in[9];
    const float* g1    = (const float*)d_in[10];
    const float* b1    = (const float*)d_in[11];
    const float* fw1   = (const float*)d_in[12];
    const float* fb1   = (const float*)d_in[13];
    const float* fw2   = (const float*)d_in[14];
    const float* fb2   = (const float*)d_in[15];
    const float* g2    = (const float*)d_in[16];
    const float* b2    = (const float*)d_in[17];
    const float* sbase = (const float*)d_in[18];
    const float* taff  = (const float*)d_in[19];
    const float* sw1   = (const float*)d_in[20];
    const float* sb1   = (const float*)d_in[21];
    const float* sw2   = (const float*)d_in[22];
    const float* sb2   = (const float*)d_in[23];

    k1_blockqkv<<<K1_BLOCKS + TR_BLOCKS, 256>>>(M, bwqkv, bbqkv, cwqkv, cwout, fw1, fw2);
    k2_blockattn<<<512, TT>>>();
    k4_crossqkv<<<BB*TT/4, 192>>>(bwout, bbout, cbqkv);
    k5_crossattn<<<1024, 128>>>();
    k6_entropy<<<1024, 128>>>();
    k7_fused<<<BB*TT/8, 256>>>(M, tok, cbout, g1, b1, fb1, fb2, g2, b2,
                               sbase, taff, sw1, sb1, sw2, sb2, (float*)d_out);
}